// round 6
// baseline (speedup 1.0000x reference)
#include <cuda_runtime.h>
#include <cuda_bf16.h>
#include <cstdint>

// Problem: N=2048, D=128, k=4, T=0.5.
// rows (queries) = 4096, cols (keys) = 8192.
// sim = norm(z[0:4096]) @ norm(z_all)^T * 2 ; mask non-target diagonals;
// loss = mean(logsumexp - pos). Logits in [-2,2] -> no max subtraction.
//
// FP8 plan: g_n8 holds e4m3(16 * zhat). acc = 256 * sim_raw.
//  - exp term: ex2(acc * 2*log2(e)/256)
//  - masked diag: subtract the SAME computed term -> exact cancellation
//  - positive logit: exact fp32 dot over bf16 rows by the owning thread

#define DIMK 128

// ---------------- device scratch (no allocations allowed) -------------------
__device__ __nv_bfloat16 g_nb[8192 * 128];  // normalized rows, bf16 (exact pos)
__device__ uint8_t g_n8[8192 * 128];        // normalized rows * 16, e4m3
__device__ float g_S[4096 * 8];             // [row][cg] exp-sum partials
__device__ float g_pos[4096 * 8];           // [row][cg] positive logit
__device__ unsigned int g_cnt;              // arrival counter (reset by last CTA)

__device__ __forceinline__ uint32_t smem_u32(const void* p) {
    uint32_t a;
    asm("{ .reg .u64 t; cvta.to.shared.u64 t, %1; cvt.u32.u64 %0, t; }"
        : "=r"(a) : "l"(p));
    return a;
}
__device__ __forceinline__ float ex2(float x) {
    float y;
    asm("ex2.approx.ftz.f32 %0, %1;" : "=f"(y) : "f"(x));
    return y;
}
__device__ __forceinline__ void ldsm_x4(uint32_t* r, uint32_t addr) {
    asm volatile("ldmatrix.sync.aligned.m8n8.x4.shared.b16 {%0,%1,%2,%3}, [%4];"
                 : "=r"(r[0]), "=r"(r[1]), "=r"(r[2]), "=r"(r[3]) : "r"(addr));
}
__device__ __forceinline__ void mma_fp8(float* c, const uint32_t* a,
                                        uint32_t b0, uint32_t b1) {
    asm volatile(
        "mma.sync.aligned.m16n8k32.row.col.f32.e4m3.e4m3.f32 "
        "{%0,%1,%2,%3}, {%4,%5,%6,%7}, {%8,%9}, {%0,%1,%2,%3};"
        : "+f"(c[0]), "+f"(c[1]), "+f"(c[2]), "+f"(c[3])
        : "r"(a[0]), "r"(a[1]), "r"(a[2]), "r"(a[3]), "r"(b0), "r"(b1));
}
__device__ __forceinline__ uint32_t pack_e4m3x4(float a, float b, float c, float d) {
    uint16_t lo, hi;
    asm("cvt.rn.satfinite.e4m3x2.f32 %0, %1, %2;" : "=h"(lo) : "f"(b), "f"(a));
    asm("cvt.rn.satfinite.e4m3x2.f32 %0, %1, %2;" : "=h"(hi) : "f"(d), "f"(c));
    return (uint32_t)lo | ((uint32_t)hi << 16);
}
__device__ __forceinline__ float bf16dot_u32(uint32_t ua, uint32_t ub) {
    float2 fa = __bfloat1622float2(*(const __nv_bfloat162*)&ua);
    float2 fb = __bfloat1622float2(*(const __nv_bfloat162*)&ub);
    return fa.x * fb.x + fa.y * fb.y;
}

#define CP_ASYNC16(sm, gp) \
    asm volatile("cp.async.cg.shared.global [%0], [%1], 16;" :: "r"(sm), "l"(gp))
#define CP_COMMIT() asm volatile("cp.async.commit_group;" ::: "memory")
#define CP_WAIT_ALL() asm volatile("cp.async.wait_all;" ::: "memory")

#define CEX (2.885390081777927f / 256.0f)   // 2*log2(e) / (16*16 fp8 scaling)

// ---------------------------------------------------------------------------
// Kernel 1: L2-normalize 8192 rows -> bf16 (exact) + e4m3*16 (MMA operand).
// 4 rows per warp. grid 256 x 256.
// ---------------------------------------------------------------------------
__global__ void normalize_kernel(const float* __restrict__ a1,
                                 const float* __restrict__ a2,
                                 const float* __restrict__ a3,
                                 const float* __restrict__ a4) {
    int w = threadIdx.x >> 5, lane = threadIdx.x & 31;
    int row0 = blockIdx.x * 32 + w * 4;
    float4 v[4];
    float ss[4];
#pragma unroll
    for (int i = 0; i < 4; i++) {
        int row = row0 + i;
        const float* src = (row < 2048) ? a1 : (row < 4096) ? a2
                          : (row < 6144) ? a3 : a4;
        v[i] = *(const float4*)(src + (row & 2047) * DIMK + lane * 4);
        ss[i] = v[i].x * v[i].x + v[i].y * v[i].y + v[i].z * v[i].z + v[i].w * v[i].w;
    }
#pragma unroll
    for (int off = 16; off; off >>= 1) {
#pragma unroll
        for (int i = 0; i < 4; i++) ss[i] += __shfl_xor_sync(~0u, ss[i], off);
    }
#pragma unroll
    for (int i = 0; i < 4; i++) {
        float inv = 1.0f / fmaxf(sqrtf(ss[i]), 1e-8f);
        float x = v[i].x * inv, y = v[i].y * inv, z = v[i].z * inv, wv = v[i].w * inv;
        __nv_bfloat162 p0 = __float22bfloat162_rn(make_float2(x, y));
        __nv_bfloat162 p1 = __float22bfloat162_rn(make_float2(z, wv));
        uint2 st;
        st.x = *(uint32_t*)&p0;
        st.y = *(uint32_t*)&p1;
        ((uint2*)(g_nb + (row0 + i) * DIMK))[lane] = st;
        ((uint32_t*)(g_n8 + (row0 + i) * DIMK))[lane] =
            pack_e4m3x4(16.f * x, 16.f * y, 16.f * z, 16.f * wv);
    }
}

// ---------------------------------------------------------------------------
// Kernel 2: FP8 HMMA GEMM + fused epilogue + last-CTA finalize.
// CTA tile = 128 rows x 1024 cols (8 subtiles of 128), K=128 in one shot.
// 256 threads = 8 warps (4 M x 2 N), warp tile 32x64, m16n8k32 e4m3.
// grid = (32 row tiles, 8 col groups) = 256 CTAs, single wave.
// ---------------------------------------------------------------------------
#define TSTRIDE 144                 // 128 fp8 + 16 pad (16B aligned, conflict-free)
#define SM_A 0
#define SM_B0 (128 * TSTRIDE)       // 18432
#define SM_B1 (2 * 128 * TSTRIDE)   // 36864
#define SM_S (3 * 128 * TSTRIDE)    // 55296: float sS[2][128]
#define SM_P (SM_S + 1024)
#define SMEM_BYTES (SM_P + 1024)    // 57344

__device__ __forceinline__ void issue_tile_load(uint32_t sb, int sm_off,
                                                int grow0, int tid) {
#pragma unroll
    for (int it = 0; it < 4; it++) {
        int idx = it * 256 + tid;           // 1024 16B vectors (128 rows x 128B)
        int r = idx >> 3, g = idx & 7;
        CP_ASYNC16(sb + sm_off + r * TSTRIDE + g * 16,
                   (const char*)(g_n8 + (grow0 + r) * DIMK + g * 16));
    }
}

__global__ void __launch_bounds__(256, 2) sim_kernel(float* __restrict__ out) {
    extern __shared__ char smem[];
    uint32_t sb = smem_u32(smem);
    float* sS = (float*)(smem + SM_S);
    float* sP = (float*)(smem + SM_P);
    __shared__ int sLast;

    int tid = threadIdx.x;
    int lane = tid & 31;
    int w = tid >> 5;
    int wm = w & 3;        // M warp (rows wm*32..+31)
    int wn = w >> 2;       // N warp (cols wn*64..+63)
    int row0 = blockIdx.x * 128;
    int cg = blockIdx.y;                  // cols [cg*1024, cg*1024+1024)

    // ---- prologue: A + B0 ----
    issue_tile_load(sb, SM_A, row0, tid);
    issue_tile_load(sb, SM_B0, cg * 1024, tid);
    CP_COMMIT();

    // ---- ldmatrix lane address bases (fp8: 16B octets, 32B per k-step) ----
    int arow = wm * 32 + ((lane >> 3) & 1) * 8 + (lane & 7);
    uint32_t baseA = sb + SM_A + arow * TSTRIDE + (lane >> 4) * 16;
    int brow = wn * 64 + ((lane >> 4) & 1) * 8 + (lane & 7);
    uint32_t baseBoff = brow * TSTRIDE + ((lane >> 3) & 1) * 16;

    int qrow = lane >> 2;          // 0..7
    // ---- per-row diagonal bookkeeping ----
    int half = row0 >> 11;
    int cblk = cg >> 1;
    bool tgt = (cblk == 1 - half);
    int dl0 = (row0 & 2047) - (cg & 1) * 1024;

    int nid[4], c_id[4], dsub[4], rloc[4];
    bool fix[4];
#pragma unroll
    for (int mi = 0; mi < 2; mi++)
#pragma unroll
        for (int h = 0; h < 2; h++) {
            int i = mi * 2 + h;
            int row_local = wm * 32 + mi * 16 + qrow + 8 * h;
            rloc[i] = row_local;
            int d = dl0 + row_local;
            dsub[i] = d >> 7;
            nid[i] = (d & 63) >> 3;
            c_id[i] = 2 * h + (d & 1);
            fix[i] = (d >= 0) && (d < 1024)
                   && (((d >> 6) & 1) == wn)
                   && (((d & 7) >> 1) == (lane & 3));
        }

    float sumReg[4] = {0.f, 0.f, 0.f, 0.f};
    float posReg[4] = {0.f, 0.f, 0.f, 0.f};

    for (int ct = 0; ct < 8; ct++) {
        CP_WAIT_ALL();
        __syncthreads();

        if (ct < 7) {
            issue_tile_load(sb, ((ct + 1) & 1) ? SM_B1 : SM_B0,
                            cg * 1024 + (ct + 1) * 128, tid);
            CP_COMMIT();
        }

        uint32_t baseB = sb + ((ct & 1) ? SM_B1 : SM_B0) + baseBoff;

        float acc[2][8][4];
#pragma unroll
        for (int mi = 0; mi < 2; mi++)
#pragma unroll
            for (int ni = 0; ni < 8; ni++)
#pragma unroll
                for (int c = 0; c < 4; c++) acc[mi][ni][c] = 0.f;

#pragma unroll
        for (int ks = 0; ks < 4; ks++) {       // K=128, 32 per mma
            uint32_t a[2][4];
            ldsm_x4(a[0], baseA + ks * 32);
            ldsm_x4(a[1], baseA + 16 * TSTRIDE + ks * 32);
            uint32_t b[4][4];
#pragma unroll
            for (int nip = 0; nip < 4; nip++)
                ldsm_x4(b[nip], baseB + nip * 16 * TSTRIDE + ks * 32);
#pragma unroll
            for (int mi = 0; mi < 2; mi++)
#pragma unroll
                for (int nip = 0; nip < 4; nip++) {
                    mma_fp8(acc[mi][2 * nip + 0], a[mi], b[nip][0], b[nip][1]);
                    mma_fp8(acc[mi][2 * nip + 1], a[mi], b[nip][2], b[nip][3]);
                }
        }

        // ---- epilogue: branch-free exp-sum + one diag fixup per row ----
#pragma unroll
        for (int mi = 0; mi < 2; mi++)
#pragma unroll
            for (int h = 0; h < 2; h++) {
                int i = mi * 2 + h;
                float s = 0.f;
#pragma unroll
                for (int ni = 0; ni < 8; ni++) {
                    s += ex2(acc[mi][ni][2 * h + 0] * CEX);
                    s += ex2(acc[mi][ni][2 * h + 1] * CEX);
                }
                sumReg[i] += s;
                if (fix[i] && dsub[i] == ct) {
                    if (tgt) {
                        // exact positive logit: fp32 dot over bf16 rows
                        int row = row0 + rloc[i];
                        int prow = cblk * 2048 + (row & 2047);
                        const uint4* pa = (const uint4*)(g_nb + row * DIMK);
                        const uint4* pb = (const uint4*)(g_nb + prow * DIMK);
                        float dsum = 0.f;
#pragma unroll
                        for (int t = 0; t < 16; t++) {
                            uint4 ua = pa[t], ub = pb[t];
                            dsum += bf16dot_u32(ua.x, ub.x) + bf16dot_u32(ua.y, ub.y)
                                  + bf16dot_u32(ua.z, ub.z) + bf16dot_u32(ua.w, ub.w);
                        }
                        posReg[i] = 2.0f * dsum;
                    } else {
                        // masked diag: subtract the SAME term -> exact cancel
                        sumReg[i] -= ex2(acc[mi][nid[i]][c_id[i]] * CEX);
                    }
                }
            }
    }

    // ---- per-row reduce across lanes and the 2 N warps ----
#pragma unroll
    for (int i = 0; i < 4; i++) {
        sumReg[i] += __shfl_xor_sync(~0u, sumReg[i], 1);
        sumReg[i] += __shfl_xor_sync(~0u, sumReg[i], 2);
        posReg[i] += __shfl_xor_sync(~0u, posReg[i], 1);
        posReg[i] += __shfl_xor_sync(~0u, posReg[i], 2);
    }
    __syncthreads();
    if ((lane & 3) == 0) {
#pragma unroll
        for (int i = 0; i < 4; i++) {
            sS[wn * 128 + rloc[i]] = sumReg[i];
            sP[wn * 128 + rloc[i]] = posReg[i];
        }
    }
    __syncthreads();
    if (tid < 128) {
        int row = row0 + tid;
        g_S[row * 8 + cg] = sS[tid] + sS[128 + tid];
        g_pos[row * 8 + cg] = sP[tid] + sP[128 + tid];
    }

    // ---- last-CTA finalize (deterministic) ----
    __threadfence();
    __syncthreads();
    if (tid == 0) sLast = (atomicAdd(&g_cnt, 1u) == 255u);
    __syncthreads();
    if (sLast) {
        __threadfence();   // acquire side
        __shared__ float wsum[8];
        float local = 0.f;
        for (int r = tid; r < 4096; r += 256) {
            const float4* s4 = (const float4*)(g_S + r * 8);
            float4 x = s4[0], y = s4[1];
            float S = (x.x + x.y) + (x.z + x.w) + (y.x + y.y) + (y.z + y.w);
            const float4* p4 = (const float4*)(g_pos + r * 8);
            float4 px = p4[0], py = p4[1];
            float p = (px.x + px.y) + (px.z + px.w) + (py.x + py.y) + (py.z + py.w);
            local += logf(S) - p;
        }
#pragma unroll
        for (int off = 16; off; off >>= 1) local += __shfl_xor_sync(~0u, local, off);
        if (lane == 0) wsum[tid >> 5] = local;
        __syncthreads();
        if (tid < 32) {
            float t = (tid < 8) ? wsum[tid] : 0.f;
#pragma unroll
            for (int off = 4; off; off >>= 1) t += __shfl_xor_sync(~0u, t, off);
            if (tid == 0) {
                out[0] = t / 4096.f;
                g_cnt = 0;               // reset for next graph replay
            }
        }
    }
}

// ---------------------------------------------------------------------------
extern "C" void kernel_launch(void* const* d_in, const int* in_sizes, int n_in,
                              void* d_out, int out_size) {
    const float* a1 = (const float*)d_in[0];
    const float* a2 = (const float*)d_in[1];
    const float* a3 = (const float*)d_in[2];
    const float* a4 = (const float*)d_in[3];

    normalize_kernel<<<256, 256>>>(a1, a2, a3, a4);

    cudaFuncSetAttribute(sim_kernel, cudaFuncAttributeMaxDynamicSharedMemorySize,
                         SMEM_BYTES);
    dim3 grid(32, 8);
    sim_kernel<<<grid, 256, SMEM_BYTES>>>((float*)d_out);
}

// round 7
// speedup vs baseline: 1.2140x; 1.2140x over previous
#include <cuda_runtime.h>
#include <cuda_fp16.h>
#include <cstdint>

// Problem: N=2048, D=128, k=4, T=0.5.
// rows (queries) = 4096, cols (keys) = 8192.
// sim = norm(z[0:4096]) @ norm(z_all)^T * 2 ; mask non-target diagonals;
// loss = mean(logsumexp - pos). Logits in [-2,2] -> no max subtraction.
//
// f16 plan: A operand = f16(2*log2(e) * zhat) (queries), B = f16(zhat) (keys).
// acc (f16) = 2*log2(e)*sim  ->  exp term = ex2(acc) via h2exp2 (packed MUFU),
// pos = acc * ln(2). Masked diag: subtract the SAME computed ex2 term.

#define DIMK 128
#define SCALEA 2.885390081777927f     // 2 * log2(e)
#define LN2F 0.6931471805599453f

// ---------------- device scratch (no allocations allowed) -------------------
__device__ __half g_a16[4096 * 128];   // scaled normalized queries
__device__ __half g_b16[8192 * 128];   // normalized keys
__device__ float g_S[4096 * 16];       // [row][cg*2+wn] exp-sum partials
__device__ float g_pos[4096 * 16];     // [row][cg*2+wn] positive logit
__device__ unsigned int g_cnt;         // arrival counter (reset by last CTA)

__device__ __forceinline__ uint32_t smem_u32(const void* p) {
    uint32_t a;
    asm("{ .reg .u64 t; cvta.to.shared.u64 t, %1; cvt.u32.u64 %0, t; }"
        : "=r"(a) : "l"(p));
    return a;
}
__device__ __forceinline__ void ldsm_x4(uint32_t* r, uint32_t addr) {
    asm volatile("ldmatrix.sync.aligned.m8n8.x4.shared.b16 {%0,%1,%2,%3}, [%4];"
                 : "=r"(r[0]), "=r"(r[1]), "=r"(r[2]), "=r"(r[3]) : "r"(addr));
}
__device__ __forceinline__ void mma_h16(uint32_t* c, const uint32_t* a,
                                        uint32_t b0, uint32_t b1) {
    asm volatile(
        "mma.sync.aligned.m16n8k16.row.col.f16.f16.f16.f16 "
        "{%0,%1}, {%2,%3,%4,%5}, {%6,%7}, {%0,%1};"
        : "+r"(c[0]), "+r"(c[1])
        : "r"(a[0]), "r"(a[1]), "r"(a[2]), "r"(a[3]), "r"(b0), "r"(b1));
}

#define CP_ASYNC16(sm, gp) \
    asm volatile("cp.async.cg.shared.global [%0], [%1], 16;" :: "r"(sm), "l"(gp))
#define CP_COMMIT() asm volatile("cp.async.commit_group;" ::: "memory")
#define CP_WAIT_ALL() asm volatile("cp.async.wait_all;" ::: "memory")

// ---------------------------------------------------------------------------
// Kernel 1: L2-normalize 8192 rows -> f16 keys; first 4096 also scaled f16
// queries. 4 rows per warp. grid 256 x 256.
// ---------------------------------------------------------------------------
__global__ void normalize_kernel(const float* __restrict__ a1,
                                 const float* __restrict__ a2,
                                 const float* __restrict__ a3,
                                 const float* __restrict__ a4) {
    int w = threadIdx.x >> 5, lane = threadIdx.x & 31;
    int row0 = blockIdx.x * 32 + w * 4;
    float4 v[4];
    float ss[4];
#pragma unroll
    for (int i = 0; i < 4; i++) {
        int row = row0 + i;
        const float* src = (row < 2048) ? a1 : (row < 4096) ? a2
                          : (row < 6144) ? a3 : a4;
        v[i] = *(const float4*)(src + (row & 2047) * DIMK + lane * 4);
        ss[i] = v[i].x * v[i].x + v[i].y * v[i].y + v[i].z * v[i].z + v[i].w * v[i].w;
    }
#pragma unroll
    for (int off = 16; off; off >>= 1) {
#pragma unroll
        for (int i = 0; i < 4; i++) ss[i] += __shfl_xor_sync(~0u, ss[i], off);
    }
#pragma unroll
    for (int i = 0; i < 4; i++) {
        int row = row0 + i;
        float inv = 1.0f / fmaxf(sqrtf(ss[i]), 1e-8f);
        float x = v[i].x * inv, y = v[i].y * inv, z = v[i].z * inv, wv = v[i].w * inv;
        __half2 b0 = __float22half2_rn(make_float2(x, y));
        __half2 b1 = __float22half2_rn(make_float2(z, wv));
        uint2 st;
        st.x = *(uint32_t*)&b0;
        st.y = *(uint32_t*)&b1;
        ((uint2*)(g_b16 + row * DIMK))[lane] = st;
        if (row < 4096) {
            __half2 s0 = __float22half2_rn(make_float2(SCALEA * x, SCALEA * y));
            __half2 s1 = __float22half2_rn(make_float2(SCALEA * z, SCALEA * wv));
            uint2 sa;
            sa.x = *(uint32_t*)&s0;
            sa.y = *(uint32_t*)&s1;
            ((uint2*)(g_a16 + row * DIMK))[lane] = sa;
        }
    }
}

// ---------------------------------------------------------------------------
// Kernel 2: f16 HMMA GEMM (f16 accumulators) + fused exp epilogue +
// last-CTA finalize. CTA tile = 128 rows x 1024 cols (8 subtiles of 128),
// K=128 in one shot. 256 threads = 8 warps (4 M x 2 N), warp tile 32x64.
// grid = (32 row tiles, 8 col groups) = 256 CTAs.
// ---------------------------------------------------------------------------
#define TSTRIDE 272                 // 128 f16 + 8 pad (conflict-free ldmatrix)
#define SM_A 0
#define SM_B0 (128 * TSTRIDE)       // 34816
#define SM_B1 (2 * 128 * TSTRIDE)   // 69632
#define SMEM_BYTES (3 * 128 * TSTRIDE)  // 104448; 2 CTA/SM

__device__ __forceinline__ void issue_tile_load(uint32_t sb, int sm_off,
                                                const __half* src, int grow0,
                                                int tid) {
#pragma unroll
    for (int it = 0; it < 8; it++) {
        int idx = it * 256 + tid;           // 2048 16B vectors (128 rows x 256B)
        int r = idx >> 4, g = idx & 15;
        CP_ASYNC16(sb + sm_off + r * TSTRIDE + g * 16,
                   (const char*)(src + (grow0 + r) * DIMK + g * 8));
    }
}

__global__ void __launch_bounds__(256, 2) sim_kernel(float* __restrict__ out) {
    extern __shared__ char smem[];
    uint32_t sb = smem_u32(smem);
    __shared__ int sLast;
    __shared__ float wsum[8];

    int tid = threadIdx.x;
    int lane = tid & 31;
    int w = tid >> 5;
    int wm = w & 3;        // M warp (rows wm*32..+31)
    int wn = w >> 2;       // N warp (cols wn*64..+63)
    int row0 = blockIdx.x * 128;
    int cg = blockIdx.y;                  // cols [cg*1024, cg*1024+1024)

    // ---- prologue: A + B0 ----
    issue_tile_load(sb, SM_A, g_a16, row0, tid);
    issue_tile_load(sb, SM_B0, g_b16, cg * 1024, tid);
    CP_COMMIT();

    // ---- ldmatrix lane address bases ----
    int arow = wm * 32 + ((lane >> 3) & 1) * 8 + (lane & 7);
    int akoct = (lane >> 4) * 8;
    uint32_t baseA = sb + SM_A + arow * TSTRIDE + akoct * 2;
    int brow = wn * 64 + ((lane >> 4) & 1) * 8 + (lane & 7);
    int bkoct = ((lane >> 3) & 1) * 8;
    uint32_t baseBoff = brow * TSTRIDE + bkoct * 2;

    int qrow = lane >> 2;          // 0..7
    // ---- per-row diagonal bookkeeping ----
    int half = row0 >> 11;
    int cblk = cg >> 1;
    bool tgt = (cblk == 1 - half);
    int dl0 = (row0 & 2047) - (cg & 1) * 1024;

    int nid[4], dhalf[4], dsub[4], rloc[4];
    bool fix[4];
#pragma unroll
    for (int mi = 0; mi < 2; mi++)
#pragma unroll
        for (int h = 0; h < 2; h++) {
            int i = mi * 2 + h;
            int row_local = wm * 32 + mi * 16 + qrow + 8 * h;
            rloc[i] = row_local;
            int d = dl0 + row_local;
            dsub[i] = d >> 7;
            nid[i] = (d & 63) >> 3;
            dhalf[i] = d & 1;
            fix[i] = (d >= 0) && (d < 1024)
                   && (((d >> 6) & 1) == wn)
                   && (((d & 7) >> 1) == (lane & 3));
        }

    float sumReg[4] = {0.f, 0.f, 0.f, 0.f};
    float posReg[4] = {0.f, 0.f, 0.f, 0.f};

    for (int ct = 0; ct < 8; ct++) {
        CP_WAIT_ALL();
        __syncthreads();

        if (ct < 7) {
            issue_tile_load(sb, ((ct + 1) & 1) ? SM_B1 : SM_B0,
                            g_b16, cg * 1024 + (ct + 1) * 128, tid);
            CP_COMMIT();
        }

        uint32_t baseB = sb + ((ct & 1) ? SM_B1 : SM_B0) + baseBoff;

        // f16 accumulators: acc[mi][ni][h] = half2 (two adjacent cols, row
        // group h). Zero-init each subtile.
        uint32_t acc[2][8][2];
#pragma unroll
        for (int mi = 0; mi < 2; mi++)
#pragma unroll
            for (int ni = 0; ni < 8; ni++) {
                acc[mi][ni][0] = 0u;
                acc[mi][ni][1] = 0u;
            }

#pragma unroll
        for (int ks = 0; ks < 8; ks++) {
            uint32_t a[2][4];
            ldsm_x4(a[0], baseA + ks * 32);
            ldsm_x4(a[1], baseA + 16 * TSTRIDE + ks * 32);
            uint32_t b[4][4];
#pragma unroll
            for (int nip = 0; nip < 4; nip++)
                ldsm_x4(b[nip], baseB + nip * 16 * TSTRIDE + ks * 32);
#pragma unroll
            for (int mi = 0; mi < 2; mi++)
#pragma unroll
                for (int nip = 0; nip < 4; nip++) {
                    mma_h16(acc[mi][2 * nip + 0], a[mi], b[nip][0], b[nip][1]);
                    mma_h16(acc[mi][2 * nip + 1], a[mi], b[nip][2], b[nip][3]);
                }
        }

        // ---- epilogue: packed ex2 + packed f16 tree sum + diag fixup ----
#pragma unroll
        for (int mi = 0; mi < 2; mi++)
#pragma unroll
            for (int h = 0; h < 2; h++) {
                int i = mi * 2 + h;
                __half2 e[8];
#pragma unroll
                for (int ni = 0; ni < 8; ni++)
                    e[ni] = h2exp2(*(__half2*)&acc[mi][ni][h]);
                __half2 t = __hadd2(__hadd2(__hadd2(e[0], e[1]), __hadd2(e[2], e[3])),
                                    __hadd2(__hadd2(e[4], e[5]), __hadd2(e[6], e[7])));
                float2 f = __half22float2(t);
                sumReg[i] += f.x + f.y;
                if (fix[i] && dsub[i] == ct) {
                    __half2 av = *(__half2*)&acc[mi][nid[i]][h];
                    if (tgt) {
                        float a = dhalf[i] ? __high2float(av) : __low2float(av);
                        posReg[i] += a * LN2F;           // pos = acc * ln2
                    } else {
                        __half2 ev = h2exp2(av);          // same term as summed
                        sumReg[i] -= dhalf[i] ? __high2float(ev) : __low2float(ev);
                    }
                }
            }
    }

    // ---- per-row reduce across the 4 col-lanes; direct global partials ----
#pragma unroll
    for (int i = 0; i < 4; i++) {
        sumReg[i] += __shfl_xor_sync(~0u, sumReg[i], 1);
        sumReg[i] += __shfl_xor_sync(~0u, sumReg[i], 2);
        posReg[i] += __shfl_xor_sync(~0u, posReg[i], 1);
        posReg[i] += __shfl_xor_sync(~0u, posReg[i], 2);
    }
    if ((lane & 3) == 0) {
#pragma unroll
        for (int i = 0; i < 4; i++) {
            int row = row0 + rloc[i];
            g_S[row * 16 + cg * 2 + wn] = sumReg[i];
            g_pos[row * 16 + cg * 2 + wn] = posReg[i];
        }
    }

    // ---- last-CTA finalize (deterministic) ----
    __threadfence();
    __syncthreads();
    if (tid == 0) sLast = (atomicAdd(&g_cnt, 1u) == 255u);
    __syncthreads();
    if (sLast) {
        __threadfence();   // acquire side
        float local = 0.f;
        for (int r = tid; r < 4096; r += 256) {
            const float4* s4 = (const float4*)(g_S + r * 16);
            const float4* p4 = (const float4*)(g_pos + r * 16);
            float S = 0.f, p = 0.f;
#pragma unroll
            for (int q = 0; q < 4; q++) {
                float4 x = s4[q], y = p4[q];
                S += (x.x + x.y) + (x.z + x.w);
                p += (y.x + y.y) + (y.z + y.w);
            }
            local += logf(S) - p;
        }
#pragma unroll
        for (int off = 16; off; off >>= 1) local += __shfl_xor_sync(~0u, local, off);
        if (lane == 0) wsum[tid >> 5] = local;
        __syncthreads();
        if (tid < 32) {
            float t = (tid < 8) ? wsum[tid] : 0.f;
#pragma unroll
            for (int off = 4; off; off >>= 1) t += __shfl_xor_sync(~0u, t, off);
            if (tid == 0) {
                out[0] = t / 4096.f;
                g_cnt = 0;               // reset for next graph replay
            }
        }
    }
}

// ---------------------------------------------------------------------------
extern "C" void kernel_launch(void* const* d_in, const int* in_sizes, int n_in,
                              void* d_out, int out_size) {
    const float* a1 = (const float*)d_in[0];
    const float* a2 = (const float*)d_in[1];
    const float* a3 = (const float*)d_in[2];
    const float* a4 = (const float*)d_in[3];

    normalize_kernel<<<256, 256>>>(a1, a2, a3, a4);

    cudaFuncSetAttribute(sim_kernel, cudaFuncAttributeMaxDynamicSharedMemorySize,
                         SMEM_BYTES);
    dim3 grid(32, 8);
    sim_kernel<<<grid, 256, SMEM_BYTES>>>((float*)d_out);
}